// round 16
// baseline (speedup 1.0000x reference)
#include <cuda_runtime.h>
#include <cuda_bf16.h>
#include <cstdint>

#define HH 128
#define WW 256
#define BB 8
#define HW (HH*WW)
#define NFUSED (BB*64*HW)
#define YP 130
#define XP 258
#define PS8 (YP*XP*8)        // elems per 8-channel padded plane (268320)

// modality strides (elems): [mod][b][oct][y][x][8]
#define X_MS  ((size_t)BB*8*PS8)
#define H1_MS ((size_t)BB*4*PS8)
#define MD_MS ((size_t)BB*2*PS8)
#define H2_MS ((size_t)BB*4*PS8)

// static device scratch (allowed)
__device__ __align__(128) __nv_bfloat16 g_x [2*BB*8*PS8];
__device__ __align__(128) __nv_bfloat16 g_h1[2*BB*4*PS8];
__device__ __align__(128) __nv_bfloat16 g_md[2*BB*2*PS8];
__device__ __align__(128) __nv_bfloat16 g_h2[2*BB*4*PS8];
__device__ __align__(128) __nv_bfloat16 g_wb[46080];
__device__ double g_loss;

// ---- helpers -------------------------------------------------------------
__device__ __forceinline__ uint32_t s2u(const void* p){return (uint32_t)__cvta_generic_to_shared(p);}
__device__ __forceinline__ void cpa16(uint32_t s, const void* g){
  asm volatile("cp.async.cg.shared.global [%0],[%1],16;"::"r"(s),"l"(g));}
__device__ __forceinline__ void cpacommit(){asm volatile("cp.async.commit_group;":::"memory");}
__device__ __forceinline__ void cpawait0(){asm volatile("cp.async.wait_group 0;":::"memory");}
__device__ __forceinline__ void fpa(){asm volatile("fence.proxy.async.shared::cta;":::"memory");}
__device__ __forceinline__ void mbinit(uint32_t a,int c){
  asm volatile("mbarrier.init.shared.b64 [%0],%1;"::"r"(a),"r"(c):"memory");}
__device__ __forceinline__ void mbtx(uint32_t a,int n){
  asm volatile("mbarrier.arrive.expect_tx.shared.b64 _,[%0],%1;"::"r"(a),"r"(n):"memory");}
__device__ __forceinline__ void mbwait(uint32_t a,int ph){
  asm volatile("{\n\t.reg .pred P;\n\t"
    "WL%=:\n\t"
    "mbarrier.try_wait.parity.acquire.cta.shared::cta.b64 P,[%0],%1,0x989680;\n\t"
    "@P bra WD%=;\n\t bra WL%=;\n\t WD%=:\n\t}"::"r"(a),"r"(ph):"memory");}
__device__ __forceinline__ void bulkcp(uint32_t d,const void* s,int n,uint32_t mb){
  asm volatile("cp.async.bulk.shared::cta.global.mbarrier::complete_tx::bytes [%0],[%1],%2,[%3];"
    ::"r"(d),"l"(s),"r"(n),"r"(mb):"memory");}

// ---- small kernels -------------------------------------------------------
__global__ void pad_all(__nv_bfloat16* px, __nv_bfloat16* ph1,
                        __nv_bfloat16* pmd, __nv_bfloat16* ph2){
  if (blockIdx.x == 0 && blockIdx.y == 0 && threadIdx.x == 0) g_loss = 0.0;
  int pid = blockIdx.y;
  __nv_bfloat16* p;
  if      (pid < 128)      p = px  + (size_t)pid*PS8;
  else if (pid < 192)      p = ph1 + (size_t)(pid-128)*PS8;
  else if (pid < 224)      p = pmd + (size_t)(pid-192)*PS8;
  else                     p = ph2 + (size_t)(pid-224)*PS8;
  const int tot = (2*XP + 2*YP)*8;
  for (int k = blockIdx.x*blockDim.x + threadIdx.x; k < tot; k += gridDim.x*blockDim.x){
    size_t e;
    if (k < XP*8) e = k;
    else if (k < 2*XP*8) e = (size_t)129*XP*8 + (k - XP*8);
    else if (k < (2*XP+YP)*8) { int z = k - 2*XP*8; e = (size_t)(z>>3)*XP*8 + (z&7); }
    else { int z = k - (2*XP+YP)*8; e = (size_t)(z>>3)*XP*8 + 257*8 + (z&7); }
    p[e] = __float2bfloat16(0.f);
  }
}

// weights: g_wb[off + ((tap*NCH+kc)*CO + co)*16 + q] = w[co][kc*16+q][tap]
__global__ void prep_w(const float* w1,const float* w2,const float* w3,const float* w4){
  int i = blockIdx.x*blockDim.x + threadIdx.x;
  int co,ci,off; const float* w;
  if (i < 18432)      { co=32; ci=64; off=0;     w=w1; }
  else if (i < 23040) { co=16; ci=32; off=18432; w=w2; }
  else if (i < 27648) { co=32; ci=16; off=23040; w=w3; }
  else if (i < 46080) { co=64; ci=32; off=27648; w=w4; }
  else return;
  int r = i - off;
  int q = r & 15; int r2 = r >> 4;
  int c = r2 % co; int r3 = r2 / co;
  int nch = ci/16;
  int kc = r3 % nch; int t = r3 / nch;
  g_wb[i] = __float2bfloat16(w[((size_t)c*ci + kc*16 + q)*9 + t]);
}

// fp32 NCHW feats -> exact fused avg (fp32, d_out) + padded NHWC-8 bf16
__global__ void __launch_bounds__(64)
conv_fuse(const float4* __restrict__ f0, const float4* __restrict__ f1,
          float4* __restrict__ out, __nv_bfloat16* __restrict__ xb)
{
  const int xq = threadIdx.x, cc = blockIdx.x;
  const int y = blockIdx.y, b = blockIdx.z;
  uint32_t oa[4][8], ob[4][8];
#pragma unroll
  for (int h = 0; h < 8; h++) {
    size_t i0 = ((size_t)(b*64 + cc*16 + 2*h)*HH + y)*(WW/4) + xq;
    size_t i1 = i0 + (size_t)HH*(WW/4);
    float4 a0 = f0[i0], a1 = f0[i1], v0 = f1[i0], v1 = f1[i1];
    out[i0] = make_float4(.5f*(a0.x+v0.x), .5f*(a0.y+v0.y), .5f*(a0.z+v0.z), .5f*(a0.w+v0.w));
    out[i1] = make_float4(.5f*(a1.x+v1.x), .5f*(a1.y+v1.y), .5f*(a1.z+v1.z), .5f*(a1.w+v1.w));
    const float* pa0=(const float*)&a0; const float* pa1=(const float*)&a1;
    const float* pv0=(const float*)&v0; const float* pv1=(const float*)&v1;
#pragma unroll
    for (int p = 0; p < 4; p++) {
      asm("cvt.rn.bf16x2.f32 %0,%1,%2;":"=r"(oa[p][h]):"f"(pa1[p]),"f"(pa0[p]));
      asm("cvt.rn.bf16x2.f32 %0,%1,%2;":"=r"(ob[p][h]):"f"(pv1[p]),"f"(pv0[p]));
    }
  }
#pragma unroll
  for (int p = 0; p < 4; p++) {
    int x = xq*4 + p;
    size_t po = ((size_t)(y+1)*XP + (x+1))*8;
    size_t pl0 = (size_t)(b*8 + cc*2)*PS8;
    uint4* da0 = (uint4*)(xb + pl0 + po);
    uint4* da1 = (uint4*)(xb + pl0 + PS8 + po);
    uint4* db0 = (uint4*)(xb + X_MS + pl0 + po);
    uint4* db1 = (uint4*)(xb + X_MS + pl0 + PS8 + po);
    da0[0] = make_uint4(oa[p][0],oa[p][1],oa[p][2],oa[p][3]);
    da1[0] = make_uint4(oa[p][4],oa[p][5],oa[p][6],oa[p][7]);
    db0[0] = make_uint4(ob[p][0],ob[p][1],ob[p][2],ob[p][3]);
    db1[0] = make_uint4(ob[p][4],ob[p][5],ob[p][6],ob[p][7]);
  }
}

__global__ void finalize_k(float* out, int n){
  float l = (float)(g_loss * (1.0/(double)NFUSED));
  for (int i = NFUSED + (int)threadIdx.x; i < n; i += (int)blockDim.x) out[i] = l;
}

// ---- mma.sync conv: 9 shift-GEMMs, bulk staging, 3-stage pipeline --------
constexpr int PL    = 10*66*16;     // 10560 plane strip bytes
constexpr int AB2   = 2*PL;         // 21120 per chunk buffer
constexpr int NSTG  = 3;
constexpr int MBOFF = NSTG*AB2;     // 63360
constexpr int WOFF3 = MBOFF + 64;   // 63424 weights base

template<int NCH,int COT,int N,bool LOSS>
__global__ void __launch_bounds__(256,2)
conv_mma(const __nv_bfloat16* __restrict__ in, size_t in_ms,
         const __nv_bfloat16* __restrict__ wq, const float* __restrict__ bias,
         __nv_bfloat16* __restrict__ outp, size_t out_ms, int noct_out,
         const __nv_bfloat16* __restrict__ ref, size_t ref_ms)
{
  extern __shared__ __align__(1024) char smem[];
  const int tid = threadIdx.x, lane = tid & 31, w = tid >> 5;
  constexpr int ZCO = COT/N;
  constexpr int NC8 = N/8;
  constexpr int NP4 = NC8/2;         // nc pairs per x4 B-load
  constexpr int NOCT_IN = 2*NCH;
  constexpr int TC = 2*NCH;
  const int zz = blockIdx.z;
  const int m = zz / (BB*ZCO);
  const int zr = zz - m*(BB*ZCO);
  const int b = zr/ZCO, co0 = (zr%ZCO)*N;
  const int x0 = blockIdx.x*64;
  const int ybase = blockIdx.y*16;
  uint32_t sb = s2u(smem);

  constexpr int WUNITS = 9*NCH*N*2;
  for (int i = tid; i < WUNITS; i += 256) {
    int blk = i/(2*N), rem = i%(2*N);
    cpa16(sb + WOFF3 + i*16, (const char*)wq + ((size_t)blk*COT + co0)*32 + rem*16);
  }
  cpacommit();

  if (tid == 0) {
    mbinit(sb+MBOFF, 1); mbinit(sb+MBOFF+8, 1); mbinit(sb+MBOFF+16, 1);
    fpa();
  }
  __syncthreads();

  const char* mbase = (const char*)(in + m*in_ms) + ((size_t)b*NOCT_IN*YP*XP)*16;
  auto stage = [&](int g){
    int yt = g / NCH, c = g - yt*NCH;
    int slot = g % NSTG;
    uint32_t mba = sb + MBOFF + slot*8;
    mbtx(mba, AB2);
    uint32_t dst = sb + slot*AB2;
    const char* src = mbase + ((size_t)((2*c)*YP + ybase + yt*8)*XP + x0)*16;
#pragma unroll
    for (int o = 0; o < 2; o++)
#pragma unroll
      for (int r = 0; r < 10; r++)
        bulkcp(dst + o*PL + r*1056, src + (size_t)(o*YP + r)*XP*16, 1056, mba);
  };
  if (tid == 0) { stage(0); if (TC > 1) stage(1); }
  cpawait0();
  __syncthreads();

  const int l4 = lane >> 2, q4 = lane & 3;
  // A ldmatrix lane addr: plane = bit4, px-half = bit3, row-in-8 = bits0-2
  const uint32_t aLane = sb + ((lane>>4)&1)*PL
        + (uint32_t)((w*66) + ((lane>>3)&1)*8 + (lane&7))*16;
  // B x4 ldmatrix lane addr: co row = bits0-2, k-half = bit3, nc-in-pair = bit4
  const uint32_t bLane = sb + WOFF3 + (lane&7)*32 + ((lane>>3)&1)*16
        + ((lane>>4)&1)*256;

  float lsum = 0.f;
  int g = 0;
#pragma unroll 1
  for (int yt = 0; yt < 2; yt++) {
    float acc[4][NC8][4];
#pragma unroll
    for (int mc=0;mc<4;mc++)
#pragma unroll
      for (int nc=0;nc<NC8;nc++)
#pragma unroll
        for (int k=0;k<4;k++) acc[mc][nc][k]=0.f;

#pragma unroll 1
    for (int c = 0; c < NCH; c++, g++) {
      if (tid == 0 && g + 2 < TC) stage(g + 2);
      mbwait(sb + MBOFF + (g % NSTG)*8, (g / NSTG) & 1);
      uint32_t aBuf = aLane + (g % NSTG)*AB2;
#pragma unroll
      for (int t = 0; t < 9; t++) {
        // batched fragment loads: all B + all A up front, then all mma
        uint32_t bf[NC8][2];
#pragma unroll
        for (int np = 0; np < NP4; np++) {
          asm volatile("ldmatrix.sync.aligned.m8n8.x4.shared.b16 {%0,%1,%2,%3},[%4];"
            : "=r"(bf[2*np][0]), "=r"(bf[2*np][1]),
              "=r"(bf[2*np+1][0]), "=r"(bf[2*np+1][1])
            : "r"(bLane + (uint32_t)((t*NCH + c)*N + np*16)*32));
        }
        uint32_t aTap = aBuf + (uint32_t)((t/3)*66 + (t%3))*16;
        uint32_t Am[4][4];
#pragma unroll
        for (int mc = 0; mc < 4; mc++) {
          asm volatile("ldmatrix.sync.aligned.m8n8.x4.shared.b16 {%0,%1,%2,%3},[%4];"
            : "=r"(Am[mc][0]),"=r"(Am[mc][1]),"=r"(Am[mc][2]),"=r"(Am[mc][3])
            : "r"(aTap + mc*256));
        }
#pragma unroll
        for (int mc = 0; mc < 4; mc++)
#pragma unroll
          for (int nc = 0; nc < NC8; nc++)
            asm("mma.sync.aligned.m16n8k16.row.col.f32.bf16.bf16.f32 "
                "{%0,%1,%2,%3},{%4,%5,%6,%7},{%8,%9},{%0,%1,%2,%3};"
                : "+f"(acc[mc][nc][0]),"+f"(acc[mc][nc][1]),
                  "+f"(acc[mc][nc][2]),"+f"(acc[mc][nc][3])
                : "r"(Am[mc][0]),"r"(Am[mc][1]),"r"(Am[mc][2]),"r"(Am[mc][3]),
                  "r"(bf[nc][0]),"r"(bf[nc][1]));
      }
      __syncthreads();
    }

    // epilogue for this y-tile (overlaps with TMA staging of next tile)
    const int y = ybase + yt*8 + w;
#pragma unroll
    for (int nc = 0; nc < NC8; nc++) {
      int ch = co0 + nc*8 + q4*2;
      float bv0 = __ldg(&bias[ch]), bv1 = __ldg(&bias[ch+1]);
#pragma unroll
      for (int mc = 0; mc < 4; mc++) {
#pragma unroll
        for (int h = 0; h < 2; h++) {
          int x = x0 + mc*16 + l4 + h*8;
          float f0v = fmaxf(acc[mc][nc][2*h]   + bv0, 0.f);
          float f1v = fmaxf(acc[mc][nc][2*h+1] + bv1, 0.f);
          size_t po = ((size_t)(y+1)*XP + (x+1))*8 + (ch & 7);
          if (LOSS) {
            size_t ri = m*ref_ms + (size_t)(b*8 + (ch>>3))*PS8 + po;
            uint32_t rv = *(const uint32_t*)(ref + ri);
            float r0 = __bfloat162float(*(const __nv_bfloat16*)&rv);
            float r1 = __bfloat162float(*((const __nv_bfloat16*)&rv + 1));
            float d0 = r0 - f0v, d1 = r1 - f1v;
            lsum += d0*d0 + d1*d1;
          } else {
            uint32_t pk;
            asm("cvt.rn.bf16x2.f32 %0,%1,%2;" : "=r"(pk) : "f"(f1v), "f"(f0v));
            size_t idx = m*out_ms + (size_t)(b*noct_out + (ch>>3))*PS8 + po;
            *(uint32_t*)(outp + idx) = pk;
          }
        }
      }
    }
  }

  if (LOSS) {
#pragma unroll
    for (int off = 16; off; off >>= 1) lsum += __shfl_down_sync(~0u, lsum, off);
    __shared__ float sr[8];
    if (lane == 0) sr[w] = lsum;
    __syncthreads();
    if (tid == 0) {
      float s = 0.f;
#pragma unroll
      for (int i = 0; i < 8; i++) s += sr[i];
      atomicAdd(&g_loss, (double)s);
    }
  }
}

// ---- launch --------------------------------------------------------------
extern "C" void kernel_launch(void* const* d_in, const int* in_sizes, int n_in,
                              void* d_out, int out_size)
{
  const float* f0 = (const float*)d_in[0];
  const float* f1 = (const float*)d_in[1];
  const float* w1 = (const float*)d_in[2];  const float* b1 = (const float*)d_in[3];
  const float* w2 = (const float*)d_in[4];  const float* b2 = (const float*)d_in[5];
  const float* w3 = (const float*)d_in[6];  const float* b3 = (const float*)d_in[7];
  const float* w4 = (const float*)d_in[8];  const float* b4 = (const float*)d_in[9];
  float* out = (float*)d_out;

  __nv_bfloat16 *xb,*h1,*md,*h2,*wb;
  cudaGetSymbolAddress((void**)&xb, g_x);
  cudaGetSymbolAddress((void**)&h1, g_h1);
  cudaGetSymbolAddress((void**)&md, g_md);
  cudaGetSymbolAddress((void**)&h2, g_h2);
  cudaGetSymbolAddress((void**)&wb, g_wb);

  const int smem1 = WOFF3 + 9*4*32*32;  // 100288
  const int smem2 = WOFF3 + 9*2*16*32;  // 72640
  const int smem3 = WOFF3 + 9*1*32*32;  // 72640
  const int smem4 = WOFF3 + 9*2*32*32;  // 81856
  cudaFuncSetAttribute(conv_mma<4,32,32,false>, cudaFuncAttributeMaxDynamicSharedMemorySize, smem1);
  cudaFuncSetAttribute(conv_mma<2,16,16,false>, cudaFuncAttributeMaxDynamicSharedMemorySize, smem2);
  cudaFuncSetAttribute(conv_mma<1,32,32,false>, cudaFuncAttributeMaxDynamicSharedMemorySize, smem3);
  cudaFuncSetAttribute(conv_mma<2,64,32,true >, cudaFuncAttributeMaxDynamicSharedMemorySize, smem4);

  pad_all<<<dim3(4,288), 256>>>(xb, h1, md, h2);
  prep_w<<<(46080+255)/256, 256>>>(w1, w2, w3, w4);
  conv_fuse<<<dim3(4, HH, BB), 64>>>((const float4*)f0, (const float4*)f1,
                                     (float4*)out, xb);
  conv_mma<4,32,32,false><<<dim3(4,8,2*BB),   256, smem1>>>(xb, X_MS,  wb+0,     b1, h1, H1_MS, 4, nullptr, 0);
  conv_mma<2,16,16,false><<<dim3(4,8,2*BB),   256, smem2>>>(h1, H1_MS, wb+18432, b2, md, MD_MS, 2, nullptr, 0);
  conv_mma<1,32,32,false><<<dim3(4,8,2*BB),   256, smem3>>>(md, MD_MS, wb+23040, b3, h2, H2_MS, 4, nullptr, 0);
  conv_mma<2,64,32,true ><<<dim3(4,8,2*BB*2), 256, smem4>>>(h2, H2_MS, wb+27648, b4, nullptr, 0, 8, xb, X_MS);
  if (out_size > NFUSED) finalize_k<<<1,32>>>(out, out_size);
}

// round 17
// speedup vs baseline: 1.0432x; 1.0432x over previous
#include <cuda_runtime.h>
#include <cuda_bf16.h>
#include <cstdint>

#define HH 128
#define WW 256
#define BB 8
#define HW (HH*WW)
#define NFUSED (BB*64*HW)
#define YP 130
#define XP 258
#define PS8 (YP*XP*8)        // elems per 8-channel padded plane (268320)

// modality strides (elems): [mod][b][oct][y][x][8]
#define X_MS  ((size_t)BB*8*PS8)
#define H1_MS ((size_t)BB*4*PS8)
#define MD_MS ((size_t)BB*2*PS8)
#define H2_MS ((size_t)BB*4*PS8)

// static device scratch (allowed)
__device__ __align__(128) __nv_bfloat16 g_x [2*BB*8*PS8];
__device__ __align__(128) __nv_bfloat16 g_h1[2*BB*4*PS8];
__device__ __align__(128) __nv_bfloat16 g_md[2*BB*2*PS8];
__device__ __align__(128) __nv_bfloat16 g_h2[2*BB*4*PS8];
__device__ __align__(128) __nv_bfloat16 g_wb[46080];
__device__ double g_loss;

// ---- helpers -------------------------------------------------------------
__device__ __forceinline__ uint32_t s2u(const void* p){return (uint32_t)__cvta_generic_to_shared(p);}
__device__ __forceinline__ void cpa16(uint32_t s, const void* g){
  asm volatile("cp.async.cg.shared.global [%0],[%1],16;"::"r"(s),"l"(g));}
__device__ __forceinline__ void cpacommit(){asm volatile("cp.async.commit_group;":::"memory");}
__device__ __forceinline__ void cpawait0(){asm volatile("cp.async.wait_group 0;":::"memory");}
__device__ __forceinline__ void fpa(){asm volatile("fence.proxy.async.shared::cta;":::"memory");}
__device__ __forceinline__ void mbinit(uint32_t a,int c){
  asm volatile("mbarrier.init.shared.b64 [%0],%1;"::"r"(a),"r"(c):"memory");}
__device__ __forceinline__ void mbtx(uint32_t a,int n){
  asm volatile("mbarrier.arrive.expect_tx.shared.b64 _,[%0],%1;"::"r"(a),"r"(n):"memory");}
__device__ __forceinline__ void mbarr(uint32_t a){
  asm volatile("mbarrier.arrive.shared.b64 _,[%0];"::"r"(a):"memory");}
__device__ __forceinline__ void mbwait(uint32_t a,int ph){
  asm volatile("{\n\t.reg .pred P;\n\t"
    "WL%=:\n\t"
    "mbarrier.try_wait.parity.acquire.cta.shared::cta.b64 P,[%0],%1,0x989680;\n\t"
    "@P bra WD%=;\n\t bra WL%=;\n\t WD%=:\n\t}"::"r"(a),"r"(ph):"memory");}
__device__ __forceinline__ void bulkcp(uint32_t d,const void* s,int n,uint32_t mb){
  asm volatile("cp.async.bulk.shared::cta.global.mbarrier::complete_tx::bytes [%0],[%1],%2,[%3];"
    ::"r"(d),"l"(s),"r"(n),"r"(mb):"memory");}

// ---- small kernels -------------------------------------------------------
__global__ void pad_all(__nv_bfloat16* px, __nv_bfloat16* ph1,
                        __nv_bfloat16* pmd, __nv_bfloat16* ph2){
  if (blockIdx.x == 0 && blockIdx.y == 0 && threadIdx.x == 0) g_loss = 0.0;
  int pid = blockIdx.y;
  __nv_bfloat16* p;
  if      (pid < 128)      p = px  + (size_t)pid*PS8;
  else if (pid < 192)      p = ph1 + (size_t)(pid-128)*PS8;
  else if (pid < 224)      p = pmd + (size_t)(pid-192)*PS8;
  else                     p = ph2 + (size_t)(pid-224)*PS8;
  const int tot = (2*XP + 2*YP)*8;
  for (int k = blockIdx.x*blockDim.x + threadIdx.x; k < tot; k += gridDim.x*blockDim.x){
    size_t e;
    if (k < XP*8) e = k;
    else if (k < 2*XP*8) e = (size_t)129*XP*8 + (k - XP*8);
    else if (k < (2*XP+YP)*8) { int z = k - 2*XP*8; e = (size_t)(z>>3)*XP*8 + (z&7); }
    else { int z = k - (2*XP+YP)*8; e = (size_t)(z>>3)*XP*8 + 257*8 + (z&7); }
    p[e] = __float2bfloat16(0.f);
  }
}

// weights: g_wb[off + ((tap*NCH+kc)*CO + co)*16 + q] = w[co][kc*16+q][tap]
__global__ void prep_w(const float* w1,const float* w2,const float* w3,const float* w4){
  int i = blockIdx.x*blockDim.x + threadIdx.x;
  int co,ci,off; const float* w;
  if (i < 18432)      { co=32; ci=64; off=0;     w=w1; }
  else if (i < 23040) { co=16; ci=32; off=18432; w=w2; }
  else if (i < 27648) { co=32; ci=16; off=23040; w=w3; }
  else if (i < 46080) { co=64; ci=32; off=27648; w=w4; }
  else return;
  int r = i - off;
  int q = r & 15; int r2 = r >> 4;
  int c = r2 % co; int r3 = r2 / co;
  int nch = ci/16;
  int kc = r3 % nch; int t = r3 / nch;
  g_wb[i] = __float2bfloat16(w[((size_t)c*ci + kc*16 + q)*9 + t]);
}

// fp32 NCHW feats -> exact fused avg (fp32, d_out) + padded NHWC-8 bf16
__global__ void __launch_bounds__(64)
conv_fuse(const float4* __restrict__ f0, const float4* __restrict__ f1,
          float4* __restrict__ out, __nv_bfloat16* __restrict__ xb)
{
  const int xq = threadIdx.x, cc = blockIdx.x;
  const int y = blockIdx.y, b = blockIdx.z;
  uint32_t oa[4][8], ob[4][8];
#pragma unroll
  for (int h = 0; h < 8; h++) {
    size_t i0 = ((size_t)(b*64 + cc*16 + 2*h)*HH + y)*(WW/4) + xq;
    size_t i1 = i0 + (size_t)HH*(WW/4);
    float4 a0 = f0[i0], a1 = f0[i1], v0 = f1[i0], v1 = f1[i1];
    out[i0] = make_float4(.5f*(a0.x+v0.x), .5f*(a0.y+v0.y), .5f*(a0.z+v0.z), .5f*(a0.w+v0.w));
    out[i1] = make_float4(.5f*(a1.x+v1.x), .5f*(a1.y+v1.y), .5f*(a1.z+v1.z), .5f*(a1.w+v1.w));
    const float* pa0=(const float*)&a0; const float* pa1=(const float*)&a1;
    const float* pv0=(const float*)&v0; const float* pv1=(const float*)&v1;
#pragma unroll
    for (int p = 0; p < 4; p++) {
      asm("cvt.rn.bf16x2.f32 %0,%1,%2;":"=r"(oa[p][h]):"f"(pa1[p]),"f"(pa0[p]));
      asm("cvt.rn.bf16x2.f32 %0,%1,%2;":"=r"(ob[p][h]):"f"(pv1[p]),"f"(pv0[p]));
    }
  }
#pragma unroll
  for (int p = 0; p < 4; p++) {
    int x = xq*4 + p;
    size_t po = ((size_t)(y+1)*XP + (x+1))*8;
    size_t pl0 = (size_t)(b*8 + cc*2)*PS8;
    uint4* da0 = (uint4*)(xb + pl0 + po);
    uint4* da1 = (uint4*)(xb + pl0 + PS8 + po);
    uint4* db0 = (uint4*)(xb + X_MS + pl0 + po);
    uint4* db1 = (uint4*)(xb + X_MS + pl0 + PS8 + po);
    da0[0] = make_uint4(oa[p][0],oa[p][1],oa[p][2],oa[p][3]);
    da1[0] = make_uint4(oa[p][4],oa[p][5],oa[p][6],oa[p][7]);
    db0[0] = make_uint4(ob[p][0],ob[p][1],ob[p][2],ob[p][3]);
    db1[0] = make_uint4(ob[p][4],ob[p][5],ob[p][6],ob[p][7]);
  }
}

__global__ void finalize_k(float* out, int n){
  float l = (float)(g_loss * (1.0/(double)NFUSED));
  for (int i = NFUSED + (int)threadIdx.x; i < n; i += (int)blockDim.x) out[i] = l;
}

// ---- mma.sync conv: 9 shift-GEMMs, bulk staging, slot-granular sync ------
constexpr int PL    = 10*66*16;     // 10560 plane strip bytes
constexpr int AB2   = 2*PL;         // 21120 per chunk buffer
constexpr int NSTG  = 3;
constexpr int MBOFF = NSTG*AB2;     // 63360: full[3] mbars
constexpr int EMB   = MBOFF + 24;   // empty[3] mbars
constexpr int WOFF3 = MBOFF + 64;   // 63424 weights base

template<int NCH,int COT,int N,bool LOSS>
__global__ void __launch_bounds__(256,2)
conv_mma(const __nv_bfloat16* __restrict__ in, size_t in_ms,
         const __nv_bfloat16* __restrict__ wq, const float* __restrict__ bias,
         __nv_bfloat16* __restrict__ outp, size_t out_ms, int noct_out,
         const __nv_bfloat16* __restrict__ ref, size_t ref_ms)
{
  extern __shared__ __align__(1024) char smem[];
  const int tid = threadIdx.x, lane = tid & 31, w = tid >> 5;
  constexpr int ZCO = COT/N;
  constexpr int NC8 = N/8;
  constexpr int NP4 = NC8/2;         // nc pairs per x4 B-load
  constexpr int NOCT_IN = 2*NCH;
  constexpr int TC = 2*NCH;
  const int zz = blockIdx.z;
  const int m = zz / (BB*ZCO);
  const int zr = zz - m*(BB*ZCO);
  const int b = zr/ZCO, co0 = (zr%ZCO)*N;
  const int x0 = blockIdx.x*64;
  const int ybase = blockIdx.y*16;
  uint32_t sb = s2u(smem);

  constexpr int WUNITS = 9*NCH*N*2;
  for (int i = tid; i < WUNITS; i += 256) {
    int blk = i/(2*N), rem = i%(2*N);
    cpa16(sb + WOFF3 + i*16, (const char*)wq + ((size_t)blk*COT + co0)*32 + rem*16);
  }
  cpacommit();

  if (tid == 0) {
    mbinit(sb+MBOFF, 1); mbinit(sb+MBOFF+8, 1); mbinit(sb+MBOFF+16, 1);
    mbinit(sb+EMB,   8); mbinit(sb+EMB+8,   8); mbinit(sb+EMB+16,   8);
    fpa();
  }
  __syncthreads();

  const char* mbase = (const char*)(in + m*in_ms) + ((size_t)b*NOCT_IN*YP*XP)*16;
  // fill slot for chunk g (tid0 only). Fill #k of a slot waits consumption #k-1.
  auto stage = [&](int g){
    int yt = g / NCH, c = g - yt*NCH;
    int slot = g % NSTG;
    int k = g / NSTG;
    if (k > 0) mbwait(sb + EMB + slot*8, (k-1)&1);
    uint32_t mba = sb + MBOFF + slot*8;
    mbtx(mba, AB2);
    uint32_t dst = sb + slot*AB2;
    const char* src = mbase + ((size_t)((2*c)*YP + ybase + yt*8)*XP + x0)*16;
#pragma unroll
    for (int o = 0; o < 2; o++)
#pragma unroll
      for (int r = 0; r < 10; r++)
        bulkcp(dst + o*PL + r*1056, src + (size_t)(o*YP + r)*XP*16, 1056, mba);
  };
  if (tid == 0) { stage(0); if (TC > 1) stage(1); }
  cpawait0();
  __syncthreads();   // weights visible to all

  const int l4 = lane >> 2, q4 = lane & 3;
  // A ldmatrix lane addr: plane = bit4, px-half = bit3, row-in-8 = bits0-2
  const uint32_t aLane = sb + ((lane>>4)&1)*PL
        + (uint32_t)((w*66) + ((lane>>3)&1)*8 + (lane&7))*16;
  // B x4 ldmatrix lane addr: co row = bits0-2, k-half = bit3, nc-in-pair = bit4
  const uint32_t bLane = sb + WOFF3 + (lane&7)*32 + ((lane>>3)&1)*16
        + ((lane>>4)&1)*256;

  float lsum = 0.f;
  int g = 0;
#pragma unroll 1
  for (int yt = 0; yt < 2; yt++) {
    float acc[4][NC8][4];
#pragma unroll
    for (int mc=0;mc<4;mc++)
#pragma unroll
      for (int nc=0;nc<NC8;nc++)
#pragma unroll
        for (int k=0;k<4;k++) acc[mc][nc][k]=0.f;

#pragma unroll 1
    for (int c = 0; c < NCH; c++, g++) {
      if (tid == 0 && g + 2 < TC) stage(g + 2);
      mbwait(sb + MBOFF + (g % NSTG)*8, (g / NSTG) & 1);
      uint32_t aBuf = aLane + (g % NSTG)*AB2;
#pragma unroll
      for (int t = 0; t < 9; t++) {
        uint32_t bf[NC8][2];
#pragma unroll
        for (int np = 0; np < NP4; np++) {
          asm volatile("ldmatrix.sync.aligned.m8n8.x4.shared.b16 {%0,%1,%2,%3},[%4];"
            : "=r"(bf[2*np][0]), "=r"(bf[2*np][1]),
              "=r"(bf[2*np+1][0]), "=r"(bf[2*np+1][1])
            : "r"(bLane + (uint32_t)((t*NCH + c)*N + np*16)*32));
        }
        uint32_t aTap = aBuf + (uint32_t)((t/3)*66 + (t%3))*16;
#pragma unroll
        for (int mc = 0; mc < 4; mc++) {
          uint32_t a0,a1,a2,a3;
          asm volatile("ldmatrix.sync.aligned.m8n8.x4.shared.b16 {%0,%1,%2,%3},[%4];"
            : "=r"(a0),"=r"(a1),"=r"(a2),"=r"(a3) : "r"(aTap + mc*256));
#pragma unroll
          for (int nc = 0; nc < NC8; nc++) {
            asm("mma.sync.aligned.m16n8k16.row.col.f32.bf16.bf16.f32 "
                "{%0,%1,%2,%3},{%4,%5,%6,%7},{%8,%9},{%0,%1,%2,%3};"
                : "+f"(acc[mc][nc][0]),"+f"(acc[mc][nc][1]),
                  "+f"(acc[mc][nc][2]),"+f"(acc[mc][nc][3])
                : "r"(a0),"r"(a1),"r"(a2),"r"(a3),"r"(bf[nc][0]),"r"(bf[nc][1]));
          }
        }
      }
      // this warp is done reading slot g%NSTG — signal empty (no block sync)
      if (lane == 0) mbarr(sb + EMB + (g % NSTG)*8);
    }

    // epilogue for this y-tile (register-only inputs; overlaps with staging)
    const int y = ybase + yt*8 + w;
#pragma unroll
    for (int nc = 0; nc < NC8; nc++) {
      int ch = co0 + nc*8 + q4*2;
      float bv0 = __ldg(&bias[ch]), bv1 = __ldg(&bias[ch+1]);
#pragma unroll
      for (int mc = 0; mc < 4; mc++) {
#pragma unroll
        for (int h = 0; h < 2; h++) {
          int x = x0 + mc*16 + l4 + h*8;
          float f0v = fmaxf(acc[mc][nc][2*h]   + bv0, 0.f);
          float f1v = fmaxf(acc[mc][nc][2*h+1] + bv1, 0.f);
          size_t po = ((size_t)(y+1)*XP + (x+1))*8 + (ch & 7);
          if (LOSS) {
            size_t ri = m*ref_ms + (size_t)(b*8 + (ch>>3))*PS8 + po;
            uint32_t rv = *(const uint32_t*)(ref + ri);
            float r0 = __bfloat162float(*(const __nv_bfloat16*)&rv);
            float r1 = __bfloat162float(*((const __nv_bfloat16*)&rv + 1));
            float d0 = r0 - f0v, d1 = r1 - f1v;
            lsum += d0*d0 + d1*d1;
          } else {
            uint32_t pk;
            asm("cvt.rn.bf16x2.f32 %0,%1,%2;" : "=r"(pk) : "f"(f1v), "f"(f0v));
            size_t idx = m*out_ms + (size_t)(b*noct_out + (ch>>3))*PS8 + po;
            *(uint32_t*)(outp + idx) = pk;
          }
        }
      }
    }
  }

  if (LOSS) {
#pragma unroll
    for (int off = 16; off; off >>= 1) lsum += __shfl_down_sync(~0u, lsum, off);
    __shared__ float sr[8];
    if (lane == 0) sr[w] = lsum;
    __syncthreads();
    if (tid == 0) {
      float s = 0.f;
#pragma unroll
      for (int i = 0; i < 8; i++) s += sr[i];
      atomicAdd(&g_loss, (double)s);
    }
  }
}

// ---- launch --------------------------------------------------------------
extern "C" void kernel_launch(void* const* d_in, const int* in_sizes, int n_in,
                              void* d_out, int out_size)
{
  const float* f0 = (const float*)d_in[0];
  const float* f1 = (const float*)d_in[1];
  const float* w1 = (const float*)d_in[2];  const float* b1 = (const float*)d_in[3];
  const float* w2 = (const float*)d_in[4];  const float* b2 = (const float*)d_in[5];
  const float* w3 = (const float*)d_in[6];  const float* b3 = (const float*)d_in[7];
  const float* w4 = (const float*)d_in[8];  const float* b4 = (const float*)d_in[9];
  float* out = (float*)d_out;

  __nv_bfloat16 *xb,*h1,*md,*h2,*wb;
  cudaGetSymbolAddress((void**)&xb, g_x);
  cudaGetSymbolAddress((void**)&h1, g_h1);
  cudaGetSymbolAddress((void**)&md, g_md);
  cudaGetSymbolAddress((void**)&h2, g_h2);
  cudaGetSymbolAddress((void**)&wb, g_wb);

  const int smem1 = WOFF3 + 9*4*32*32;  // 100288
  const int smem2 = WOFF3 + 9*2*16*32;  // 72640
  const int smem3 = WOFF3 + 9*1*32*32;  // 72640
  const int smem4 = WOFF3 + 9*2*32*32;  // 81856
  cudaFuncSetAttribute(conv_mma<4,32,32,false>, cudaFuncAttributeMaxDynamicSharedMemorySize, smem1);
  cudaFuncSetAttribute(conv_mma<2,16,16,false>, cudaFuncAttributeMaxDynamicSharedMemorySize, smem2);
  cudaFuncSetAttribute(conv_mma<1,32,32,false>, cudaFuncAttributeMaxDynamicSharedMemorySize, smem3);
  cudaFuncSetAttribute(conv_mma<2,64,32,true >, cudaFuncAttributeMaxDynamicSharedMemorySize, smem4);

  pad_all<<<dim3(4,288), 256>>>(xb, h1, md, h2);
  prep_w<<<(46080+255)/256, 256>>>(w1, w2, w3, w4);
  conv_fuse<<<dim3(4, HH, BB), 64>>>((const float4*)f0, (const float4*)f1,
                                     (float4*)out, xb);
  conv_mma<4,32,32,false><<<dim3(4,8,2*BB),   256, smem1>>>(xb, X_MS,  wb+0,     b1, h1, H1_MS, 4, nullptr, 0);
  conv_mma<2,16,16,false><<<dim3(4,8,2*BB),   256, smem2>>>(h1, H1_MS, wb+18432, b2, md, MD_MS, 2, nullptr, 0);
  conv_mma<1,32,32,false><<<dim3(4,8,2*BB),   256, smem3>>>(md, MD_MS, wb+23040, b3, h2, H2_MS, 4, nullptr, 0);
  conv_mma<2,64,32,true ><<<dim3(4,8,2*BB*2), 256, smem4>>>(h2, H2_MS, wb+27648, b4, nullptr, 0, 8, xb, X_MS);
  if (out_size > NFUSED) finalize_k<<<1,32>>>(out, out_size);
}